// round 3
// baseline (speedup 1.0000x reference)
#include <cuda_runtime.h>
#include <cstdint>

// ---------------- problem constants ----------------
#define IN_F   4096
#define OUT_F  4096
#define M_TOT  8192
#define KITERS 128          // 4096 / BK
#define BK     32
#define BM     128
#define BN     128
#define NTH    128          // 4 warps

// transposed sign bitmask: packT[kword * 4096 + o], kword = k/32
__device__ uint32_t g_packT[(size_t)KITERS * OUT_F];   // 2 MB

// ---------------- helpers ----------------
static __device__ __forceinline__ uint32_t smem_u32(const void* p) {
    uint32_t a;
    asm("{ .reg .u64 t; cvta.to.shared.u64 t, %1; cvt.u32.u64 %0, t; }"
        : "=r"(a) : "l"(p));
    return a;
}

static __device__ __forceinline__ uint32_t f2tf32_rna(float f) {
    uint32_t u;
    asm("cvt.rna.tf32.f32 %0, %1;" : "=r"(u) : "f"(f));
    return u;
}

#define CP_ASYNC16(dst, src) \
    asm volatile("cp.async.cg.shared.global [%0], [%1], 16;" :: "r"(dst), "l"(src))
#define CP_COMMIT()  asm volatile("cp.async.commit_group;" ::: "memory")
#define CP_WAIT1()   asm volatile("cp.async.wait_group 1;" ::: "memory")

static __device__ __forceinline__ void mma_tf32(float* d, const uint32_t* a,
                                                const uint32_t* b) {
    asm volatile(
        "mma.sync.aligned.m16n8k8.row.col.f32.tf32.tf32.f32 "
        "{%0,%1,%2,%3}, {%4,%5,%6,%7}, {%8,%9}, {%0,%1,%2,%3};"
        : "+f"(d[0]), "+f"(d[1]), "+f"(d[2]), "+f"(d[3])
        : "r"(a[0]), "r"(a[1]), "r"(a[2]), "r"(a[3]), "r"(b[0]), "r"(b[1]));
}

// ============================================================
// Kernel 1: pack sign bits, TRANSPOSED: packT[kw * 4096 + o]
// bit b of word (o, kw) = 1 iff sign_weights[o, kw*32 + b] > 0
// ============================================================
__global__ void __launch_bounds__(256)
pack_signs_kernel(const float* __restrict__ sw) {
    uint32_t W = blockIdx.x * 8u + (threadIdx.x >> 5);   // word index 0..524287
    uint32_t lane = threadIdx.x & 31;
    uint32_t o = W >> 7;          // row 0..4095
    uint32_t kw = W & 127;        // kword 0..127
    float v = sw[(size_t)o * IN_F + kw * 32 + lane];
    uint32_t m = __ballot_sync(0xFFFFFFFFu, v > 0.0f);
    if (lane == 0) g_packT[(size_t)kw * OUT_F + o] = m;
}

// ============================================================
// Kernel 2: tf32 mma.sync GEMM  Y = X @ W^T
//   A = X tile (cp.async fp32, RNA->tf32 on fragment load)
//   B tile expanded in SMEM from bitmask: +/- rna(scale)
// CTA tile 128x128x32, 4 warps of 64x64.
// grid 2048: mt = bx>>5, nt = bx&31 (X-tile reuse across adjacent CTAs)
// ============================================================
__global__ void __launch_bounds__(NTH, 2)
bitlinear_mma_kernel(const float* __restrict__ x,
                     const float* __restrict__ scales,
                     float* __restrict__ out) {
    extern __shared__ float smf[];
    float* As = smf;                 // 3 stages * 4096 floats (16KB each)
    float* Bs = smf + 3 * 4096;      // 2 stages * 4096 floats
    const uint32_t smem_base = smem_u32(smf);

    const int tid = threadIdx.x;
    const int wid = tid >> 5;
    const int lane = tid & 31;
    const int g = lane >> 2;         // 0..7
    const int t = lane & 3;          // 0..3
    const int wm_i = wid >> 1;       // 0..1
    const int wn_i = wid & 1;        // 0..1

    const int mt = blockIdx.x >> 5;
    const int nt = blockIdx.x & 31;
    const int m0 = mt * BM;
    const int o0 = nt * BN;

    // ---- A cp.async addressing (thread-constant parts) ----
    const int arow = tid >> 3;                               // 0..15
    const int acol = ((tid & 7) * 4) ^ (4 * (arow & 7));     // swizzled col (floats)
    const float* xsrc0 = x + (size_t)(m0 + arow) * IN_F + (tid & 7) * 4;
    const uint32_t adst0 = smem_base + (uint32_t)((arow * 32 + acol) << 2);

    // ---- B expansion addressing ----
    const int brow = tid;                                    // B row 0..127 (o = o0+tid)
    const int bxor = 4 * (brow & 7);
    const int o = o0 + brow;
    const uint32_t* wsrc = g_packT + o;                      // + it*4096
    const float* ssrc = scales + (size_t)o * (IN_F / 128);   // + it>>2

    float acc[4][8][4];
    #pragma unroll
    for (int mi = 0; mi < 4; ++mi)
        #pragma unroll
        for (int nj = 0; nj < 8; ++nj)
            #pragma unroll
            for (int r = 0; r < 4; ++r) acc[mi][nj][r] = 0.0f;

    // ---- prologue: stage B(0) regs, issue A(0) ----
    uint32_t cur_w = wsrc[0];
    uint32_t cur_sp = f2tf32_rna(ssrc[0]);
    {
        #pragma unroll
        for (int j = 0; j < 8; ++j)
            CP_ASYNC16(adst0 + j * 2048, (const char*)(xsrc0 + (size_t)j * 16 * IN_F));
        CP_COMMIT();
    }

    int sa = 0;        // A stage of current iter (0..2)
    int bsel = 0;      // B buffer offset (0 or 4096)

    #pragma unroll 1
    for (int it = 0; it < KITERS; ++it) {
        // ---- 1) expand B(it) into Bs[bsel] ----
        {
            const uint32_t sp = cur_sp, sn = cur_sp ^ 0x80000000u;
            const uint32_t w = cur_w;
            float* bp = Bs + bsel + brow * 32;
            #pragma unroll
            for (int j = 0; j < 8; ++j) {
                uint4 q;
                q.x = ((w >> (j * 4 + 0)) & 1u) ? sp : sn;
                q.y = ((w >> (j * 4 + 1)) & 1u) ? sp : sn;
                q.z = ((w >> (j * 4 + 2)) & 1u) ? sp : sn;
                q.w = ((w >> (j * 4 + 3)) & 1u) ? sp : sn;
                *reinterpret_cast<uint4*>(bp + ((4 * j) ^ bxor)) = q;
            }
        }

        // ---- 2) prefetch A(it+1) + B regs(it+1) ----
        if (it < KITERS - 1) {
            const int sn3 = (sa == 2) ? 0 : sa + 1;
            const uint32_t adst = adst0 + (uint32_t)(sn3 * 16384);
            const float* src = xsrc0 + (size_t)(it + 1) * BK;
            #pragma unroll
            for (int j = 0; j < 8; ++j)
                CP_ASYNC16(adst + j * 2048, (const char*)(src + (size_t)j * 16 * IN_F));
            cur_w = wsrc[(size_t)(it + 1) * OUT_F];
            cur_sp = f2tf32_rna(ssrc[(it + 1) >> 2]);
        }
        CP_COMMIT();

        // ---- 3) wait A(it), barrier ----
        CP_WAIT1();
        __syncthreads();

        // ---- 4) compute ----
        {
            const float* A = As + sa * 4096;
            const float* B = Bs + bsel;
            #pragma unroll
            for (int ks = 0; ks < 4; ++ks) {
                const int e0 = (8 * ks + t) ^ (4 * g);
                const int e1 = (8 * ks + t + 4) ^ (4 * g);

                uint32_t af[4][4];
                #pragma unroll
                for (int mi = 0; mi < 4; ++mi) {
                    const int ro = (wm_i * 64 + mi * 16 + g) * 32;
                    af[mi][0] = f2tf32_rna(A[ro + e0]);
                    af[mi][1] = f2tf32_rna(A[ro + 256 + e0]);
                    af[mi][2] = f2tf32_rna(A[ro + e1]);
                    af[mi][3] = f2tf32_rna(A[ro + 256 + e1]);
                }
                uint32_t bf[8][2];
                #pragma unroll
                for (int nj = 0; nj < 8; ++nj) {
                    const int rb = (wn_i * 64 + nj * 8 + g) * 32;
                    bf[nj][0] = __float_as_uint(B[rb + e0]);
                    bf[nj][1] = __float_as_uint(B[rb + e1]);
                }
                #pragma unroll
                for (int mi = 0; mi < 4; ++mi)
                    #pragma unroll
                    for (int nj = 0; nj < 8; ++nj)
                        mma_tf32(acc[mi][nj], af[mi], bf[nj]);
            }
        }

        sa = (sa == 2) ? 0 : sa + 1;
        bsel ^= 4096;
    }

    // ---- epilogue: direct STG.64 ----
    #pragma unroll
    for (int mi = 0; mi < 4; ++mi) {
        const int row = m0 + wm_i * 64 + mi * 16 + g;
        #pragma unroll
        for (int nj = 0; nj < 8; ++nj) {
            const int col = o0 + wn_i * 64 + nj * 8 + 2 * t;
            float2 v0 = make_float2(acc[mi][nj][0], acc[mi][nj][1]);
            float2 v1 = make_float2(acc[mi][nj][2], acc[mi][nj][3]);
            *reinterpret_cast<float2*>(out + (size_t)row * OUT_F + col) = v0;
            *reinterpret_cast<float2*>(out + (size_t)(row + 8) * OUT_F + col) = v1;
        }
    }
}

// ============================================================
// launch
// ============================================================
extern "C" void kernel_launch(void* const* d_in, const int* in_sizes, int n_in,
                              void* d_out, int out_size) {
    const float* x      = (const float*)d_in[0];   // [4,2048,4096] fp32
    const float* sw     = (const float*)d_in[1];   // [4096,4096] fp32 (+/-1)
    const float* scales = (const float*)d_in[2];   // [131072] fp32
    float* out = (float*)d_out;

    cudaFuncSetAttribute(bitlinear_mma_kernel,
                         cudaFuncAttributeMaxDynamicSharedMemorySize, 81920);

    // 1) pack signs transposed: 524288 words / 8 warps per block
    pack_signs_kernel<<<65536, 256>>>(sw);

    // 2) GEMM: 64 M-tiles x 32 N-tiles
    bitlinear_mma_kernel<<<(M_TOT / BM) * (OUT_F / BN), NTH, 81920>>>(x, scales, out);
}

// round 4
// speedup vs baseline: 1.9327x; 1.9327x over previous
#include <cuda_runtime.h>
#include <cuda_fp16.h>
#include <cstdint>

// ---------------- problem constants ----------------
#define IN_F   4096
#define OUT_F  4096
#define M_TOT  8192
#define BK     64           // fp16 k-slice: 128B rows (8 x 16B chunks)
#define KITERS (IN_F / BK)  // 64
#define BM     128
#define BN     128
#define NTH    128          // 4 warps, 64x64 warp tiles

// ---------------- static device scratch ----------------
__device__ uint32_t g_packT[(size_t)(IN_F / 32) * OUT_F];   // 2 MB, [kword][o]
__device__ __half   g_xh[(size_t)M_TOT * IN_F];             // 64 MB, X in fp16

// ---------------- SMEM byte offsets ----------------
// A: 3 stages * 128 rows * 128B = 49152 ; B: 2 stages * 16384 = 32768
#define SMA(stage)  ((stage) * 16384)
#define SMB(sel)    (49152 + (sel))
#define SM_TOTAL    81920

// ---------------- helpers ----------------
static __device__ __forceinline__ uint32_t smem_u32(const void* p) {
    uint32_t a;
    asm("{ .reg .u64 t; cvta.to.shared.u64 t, %1; cvt.u32.u64 %0, t; }"
        : "=r"(a) : "l"(p));
    return a;
}

#define CP_ASYNC16(dst, src) \
    asm volatile("cp.async.cg.shared.global [%0], [%1], 16;" :: "r"(dst), "l"(src))
#define CP_COMMIT()  asm volatile("cp.async.commit_group;" ::: "memory")
#define CP_WAIT1()   asm volatile("cp.async.wait_group 1;" ::: "memory")

static __device__ __forceinline__ void ldsm_x4(uint32_t* r, uint32_t addr) {
    asm volatile("ldmatrix.sync.aligned.m8n8.x4.shared.b16 {%0,%1,%2,%3}, [%4];"
                 : "=r"(r[0]), "=r"(r[1]), "=r"(r[2]), "=r"(r[3]) : "r"(addr));
}

static __device__ __forceinline__ void mma_fp16(float* d, const uint32_t* a,
                                                const uint32_t* b) {
    asm volatile(
        "mma.sync.aligned.m16n8k16.row.col.f32.f16.f16.f32 "
        "{%0,%1,%2,%3}, {%4,%5,%6,%7}, {%8,%9}, {%0,%1,%2,%3};"
        : "+f"(d[0]), "+f"(d[1]), "+f"(d[2]), "+f"(d[3])
        : "r"(a[0]), "r"(a[1]), "r"(a[2]), "r"(a[3]), "r"(b[0]), "r"(b[1]));
}

// ============================================================
// Kernel 0: convert X fp32 -> fp16 (RN)
// ============================================================
__global__ void __launch_bounds__(256)
convert_x_kernel(const float4* __restrict__ x4) {
    size_t i = (size_t)blockIdx.x * 256 + threadIdx.x;   // 8 floats each
    float4 a = x4[2 * i];
    float4 b = x4[2 * i + 1];
    __half2 h0 = __floats2half2_rn(a.x, a.y);
    __half2 h1 = __floats2half2_rn(a.z, a.w);
    __half2 h2 = __floats2half2_rn(b.x, b.y);
    __half2 h3 = __floats2half2_rn(b.z, b.w);
    uint4 q;
    q.x = *reinterpret_cast<uint32_t*>(&h0);
    q.y = *reinterpret_cast<uint32_t*>(&h1);
    q.z = *reinterpret_cast<uint32_t*>(&h2);
    q.w = *reinterpret_cast<uint32_t*>(&h3);
    *reinterpret_cast<uint4*>(&g_xh[i * 8]) = q;
}

// ============================================================
// Kernel 1: pack sign bits, TRANSPOSED: packT[kw * 4096 + o]
// bit b of word (o, kw) = 1 iff sign_weights[o, kw*32 + b] > 0
// ============================================================
__global__ void __launch_bounds__(256)
pack_signs_kernel(const float* __restrict__ sw) {
    uint32_t W = blockIdx.x * 8u + (threadIdx.x >> 5);   // word 0..524287
    uint32_t lane = threadIdx.x & 31;
    uint32_t o = W >> 7;
    uint32_t kw = W & 127;
    float v = sw[(size_t)o * IN_F + kw * 32 + lane];
    uint32_t m = __ballot_sync(0xFFFFFFFFu, v > 0.0f);
    if (lane == 0) g_packT[(size_t)kw * OUT_F + o] = m;
}

// ============================================================
// Kernel 2: fp16 mma.sync GEMM  Y = Xh @ W^T
// CTA 128x128xBK64, 4 warps 64x64. B expanded in SMEM from bitmask.
// SMEM layout: rows of 128B, chunk_phys = chunk ^ (row & 7)
// ============================================================
__global__ void __launch_bounds__(NTH, 2)
bitlinear_mma_kernel(const float* __restrict__ scales,
                     float* __restrict__ out) {
    extern __shared__ char smem[];
    const uint32_t smem_base = smem_u32(smem);

    const int tid = threadIdx.x;
    const int wid = tid >> 5;
    const int lane = tid & 31;
    const int g = lane >> 2;
    const int t = lane & 3;
    const int wm_i = wid >> 1;
    const int wn_i = wid & 1;

    const int mt = blockIdx.x >> 5;
    const int nt = blockIdx.x & 31;
    const int m0 = mt * BM;
    const int o0 = nt * BN;

    // ---- A cp.async addressing: 1024 chunks, 8 per thread ----
    // lin = tid + 128*j : row = lin>>3 (0..127), chunk c = lin&7
    const int ar = tid >> 3;            // base rows: this thread covers rows ar + 16*j
    const int ac = tid & 7;
    const __half* xsrc0 = g_xh + (size_t)(m0 + ar) * IN_F + ac * 8;
    const uint32_t adst_off0 = (uint32_t)(ar * 128 + ((ac ^ (ar & 7)) << 4));

    // ---- B expansion addressing ----
    const int brow = tid;               // o = o0 + tid
    const int o = o0 + brow;
    const uint32_t* wsrc = g_packT + o; // + (2it+h)*OUT_F
    const float* ssrc = scales + (size_t)o * (IN_F / 128);

    float acc[4][8][4];
    #pragma unroll
    for (int mi = 0; mi < 4; ++mi)
        #pragma unroll
        for (int nj = 0; nj < 8; ++nj)
            #pragma unroll
            for (int r = 0; r < 4; ++r) acc[mi][nj][r] = 0.0f;

    // ---- ldmatrix lane-address components (loop-invariant) ----
    // A: row = wm_i*64 + mi*16 + (lane&15); chunk = 2*ks + (lane>>4)
    const int a_row_l = wm_i * 64 + (lane & 15);
    const int a_hl = lane >> 4;                 // 0/1
    // B: row = wn_i*64 + njp*16 + (lane&7) + ((lane>>4)&1)*8; chunk = 2ks + ((lane>>3)&1)
    const int b_row_l = wn_i * 64 + (lane & 7) + ((lane >> 4) & 1) * 8;
    const int b_hl = (lane >> 3) & 1;

    // ---- prologue ----
    uint32_t cw0 = wsrc[0];
    uint32_t cw1 = wsrc[OUT_F];
    __half hs = __float2half_rn(ssrc[0]);
    uint32_t PP; { __half2 pp = __half2half2(hs); PP = *reinterpret_cast<uint32_t*>(&pp); }
    {
        #pragma unroll
        for (int j = 0; j < 8; ++j)
            CP_ASYNC16(smem_base + adst_off0 + (uint32_t)(j * 2048),
                       (const char*)(xsrc0 + (size_t)j * 16 * IN_F));
        CP_COMMIT();
    }

    int sa = 0;
    int bsel = 0;

    #pragma unroll 1
    for (int it = 0; it < KITERS; ++it) {
        // ---- 1) expand B(it) into SMB(bsel), row = brow ----
        {
            char* bp = smem + SMB(bsel) + brow * 128;
            const int rx = brow & 7;
            #pragma unroll
            for (int c = 0; c < 8; ++c) {
                const uint32_t w = (c < 4) ? cw0 : cw1;
                const uint32_t wi = ~(w >> ((c & 3) * 8));
                uint4 q;
                {
                    uint32_t tb = wi;
                    q.x = PP ^ (((tb & 1u) << 15) | ((tb & 2u) << 30));
                    tb >>= 2;
                    q.y = PP ^ (((tb & 1u) << 15) | ((tb & 2u) << 30));
                    tb >>= 2;
                    q.z = PP ^ (((tb & 1u) << 15) | ((tb & 2u) << 30));
                    tb >>= 2;
                    q.w = PP ^ (((tb & 1u) << 15) | ((tb & 2u) << 30));
                }
                *reinterpret_cast<uint4*>(bp + ((c ^ rx) << 4)) = q;
            }
        }

        // ---- 2) prefetch A(it+1) + B words(it+1) ----
        if (it < KITERS - 1) {
            const int sn3 = (sa == 2) ? 0 : sa + 1;
            const uint32_t adst = smem_base + (uint32_t)SMA(sn3) + adst_off0;
            const __half* src = xsrc0 + (size_t)(it + 1) * BK;
            #pragma unroll
            for (int j = 0; j < 8; ++j)
                CP_ASYNC16(adst + (uint32_t)(j * 2048),
                           (const char*)(src + (size_t)j * 16 * IN_F));
            cw0 = wsrc[(size_t)(2 * it + 2) * OUT_F];
            cw1 = wsrc[(size_t)(2 * it + 3) * OUT_F];
            hs = __float2half_rn(ssrc[(it + 1) >> 1]);
            __half2 pp = __half2half2(hs);
            PP = *reinterpret_cast<uint32_t*>(&pp);
        }
        CP_COMMIT();

        // ---- 3) wait A(it), barrier ----
        CP_WAIT1();
        __syncthreads();

        // ---- 4) compute: 4 ksteps of k16 ----
        {
            const uint32_t abase = smem_base + (uint32_t)SMA(sa);
            const uint32_t bbase = smem_base + (uint32_t)SMB(bsel);
            #pragma unroll
            for (int ks = 0; ks < 4; ++ks) {
                uint32_t af[4][4];
                #pragma unroll
                for (int mi = 0; mi < 4; ++mi) {
                    const int r = a_row_l + mi * 16;
                    const int ch = (2 * ks + a_hl) ^ (r & 7);
                    ldsm_x4(af[mi], abase + (uint32_t)(r * 128 + (ch << 4)));
                }
                uint32_t bf[4][4];
                #pragma unroll
                for (int njp = 0; njp < 4; ++njp) {
                    const int r = b_row_l + njp * 16;
                    const int ch = (2 * ks + b_hl) ^ (r & 7);
                    ldsm_x4(bf[njp], bbase + (uint32_t)(r * 128 + (ch << 4)));
                }
                #pragma unroll
                for (int mi = 0; mi < 4; ++mi)
                    #pragma unroll
                    for (int njp = 0; njp < 4; ++njp) {
                        mma_fp16(acc[mi][2 * njp + 0], af[mi], &bf[njp][0]);
                        mma_fp16(acc[mi][2 * njp + 1], af[mi], &bf[njp][2]);
                    }
            }
        }

        sa = (sa == 2) ? 0 : sa + 1;
        bsel ^= 16384;
    }

    // ---- epilogue: direct STG.64 ----
    #pragma unroll
    for (int mi = 0; mi < 4; ++mi) {
        const int row = m0 + wm_i * 64 + mi * 16 + g;
        #pragma unroll
        for (int nj = 0; nj < 8; ++nj) {
            const int col = o0 + wn_i * 64 + nj * 8 + 2 * t;
            float2 v0 = make_float2(acc[mi][nj][0], acc[mi][nj][1]);
            float2 v1 = make_float2(acc[mi][nj][2], acc[mi][nj][3]);
            *reinterpret_cast<float2*>(out + (size_t)row * OUT_F + col) = v0;
            *reinterpret_cast<float2*>(out + (size_t)(row + 8) * OUT_F + col) = v1;
        }
    }
}

// ============================================================
// launch
// ============================================================
extern "C" void kernel_launch(void* const* d_in, const int* in_sizes, int n_in,
                              void* d_out, int out_size) {
    const float* x      = (const float*)d_in[0];
    const float* sw     = (const float*)d_in[1];
    const float* scales = (const float*)d_in[2];
    float* out = (float*)d_out;

    cudaFuncSetAttribute(bitlinear_mma_kernel,
                         cudaFuncAttributeMaxDynamicSharedMemorySize, SM_TOTAL);

    // 0) X -> fp16 (33.5M elems, 8 per thread)
    convert_x_kernel<<<(M_TOT * (size_t)IN_F) / (8 * 256), 256>>>(
        (const float4*)x);

    // 1) pack signs transposed
    pack_signs_kernel<<<65536, 256>>>(sw);

    // 2) GEMM: 64 M-tiles x 32 N-tiles
    bitlinear_mma_kernel<<<(M_TOT / BM) * (OUT_F / BN), NTH, SM_TOTAL>>>(scales, out);
}